// round 10
// baseline (speedup 1.0000x reference)
#include <cuda_runtime.h>
#include <cuda_fp16.h>
#include <cstdint>

// Problem constants
#define CC   32
#define HH   80
#define WW   80
#define KK   4
#define HP   77            // HH-KK+1
#define NP   (HP*HP)       // 5929 patches
#define DD   (CC*KK*KK)    // 512
#define MW   81            // mask width (H+1)
#define EPSF 1e-6f
#define HW   (HH*WW)
#define SCSTRIDE 6016      // padded candidate stride
#define SCROWS   6016      // padded query rows

// ---------------- device scratch (allocation-free rule) ----------------------
__device__ __align__(16) __half g_Ah[NP * DD];   // compacted queries (high), fp16
__device__ __align__(16) __half g_Bh[NP * DD];   // compacted candidates (low), fp16
__device__ float              g_scores[(size_t)SCROWS * SCSTRIDE]; // approx scores
__device__ float              g_invnorm[NP];
__device__ float              g_margin[NP];       // 3 * 2^-10 * ||q_p||
__device__ unsigned           g_qmax[NP];         // mono(approx max) per query patch
__device__ unsigned char      g_valid[NP];
__device__ unsigned long long g_keys[NP];
__device__ int                g_qlist[NP];
__device__ int                g_clist[NP];
__device__ int                g_qcount;           // zero-init at load; reset by output
__device__ int                g_ccount;

// ---------------- helpers -----------------------------------------------------
__device__ __forceinline__ unsigned mono(float f) {
    unsigned b = __float_as_uint(f);
    return (b & 0x80000000u) ? ~b : (b | 0x80000000u);
}
__device__ __forceinline__ float demono(unsigned u) {
    unsigned b = (u & 0x80000000u) ? (u & 0x7FFFFFFFu) : ~u;
    return __uint_as_float(b);
}
__device__ __forceinline__ uint32_t smem_u32(const void* p) {
    uint32_t a;
    asm("{ .reg .u64 t; cvta.to.shared.u64 t, %1; cvt.u32.u64 %0, t; }"
        : "=r"(a) : "l"(p));
    return a;
}
__device__ __forceinline__ void mma16816h(float* c, const uint32_t* a, const uint32_t* b) {
    asm volatile(
        "mma.sync.aligned.m16n8k16.row.col.f32.f16.f16.f32 "
        "{%0,%1,%2,%3}, {%4,%5,%6,%7}, {%8,%9}, {%0,%1,%2,%3};"
        : "+f"(c[0]), "+f"(c[1]), "+f"(c[2]), "+f"(c[3])
        : "r"(a[0]), "r"(a[1]), "r"(a[2]), "r"(a[3]), "r"(b[0]), "r"(b[1]));
}
__device__ __forceinline__ void cp16(uint32_t dst, const void* src) {
    asm volatile("cp.async.cg.shared.global [%0], [%1], 16;" :: "r"(dst), "l"(src));
}
#define CP_COMMIT() asm volatile("cp.async.commit_group;" ::: "memory")
#define CP_WAIT1()  asm volatile("cp.async.wait_group 1;" ::: "memory")
#define CP_WAIT0()  asm volatile("cp.async.wait_group 0;" ::: "memory")

// smem layout for the GEMM kernel (dynamic)
#define SM_CINV   0          // 64 floats
#define SM_QS     256        // 32 ints
#define SM_BUF    1024
#define BUFA_SZ   4096       // 32 rows x 128B (64 fp16)
#define BUFB_SZ   8192       // 64 rows x 128B
#define STAGE_SZ  (BUFA_SZ + BUFB_SZ)           // 12288
#define SMEM_TOTAL (SM_BUF + 2 * STAGE_SZ)      // 25600

// ---------------- K1: fused prep — warp per patch ----------------------------
// mask flags + compaction + fp16 gather + norms, all in one pass.
__global__ void __launch_bounds__(256) prep_kernel(const float* __restrict__ low,
                                                   const float* __restrict__ high,
                                                   const int* __restrict__ mask) {
    int p = (blockIdx.x * blockDim.x + threadIdx.x) >> 5;
    int l = threadIdx.x & 31;
    if (p >= NP) return;
    int pi = p / HP, pj = p % HP;

    int m00 = mask[pi * MW + pj];
    int m01 = mask[pi * MW + pj + KK];
    int m10 = mask[(pi + KK) * MW + pj];
    int m11 = mask[(pi + KK) * MW + pj + KK];
    bool iscand = (m00 != 1);
    bool isq    = (m00 != 0) && (m01 != 0) && (m10 != 0) && (m11 != 0);

    int ci = 0, qi = 0;
    if (l == 0) {
        g_keys[p]  = ((unsigned long long)mono(-1e9f) << 32) | 0xFFFFFFFFull;
        g_valid[p] = (unsigned char)isq;
        g_qmax[p]  = 0u;
        if (iscand) { ci = atomicAdd(&g_ccount, 1); g_clist[ci] = p; }
        if (isq)    { qi = atomicAdd(&g_qcount, 1); g_qlist[qi] = p; }
    }
    ci = __shfl_sync(0xFFFFFFFFu, ci, 0);
    qi = __shfl_sync(0xFFFFFFFFu, qi, 0);

    if (iscand) {
        float ss = 0.f;
        #pragma unroll
        for (int g = 0; g < 4; g++) {
            int d0 = g * 128 + l * 4;              // 4 consecutive elems, dj=0..3
            int c = d0 >> 4, di = (d0 >> 2) & 3;
            const float* rp = low + c * HW + (pi + di) * WW + pj;
            unsigned short hb[4];
            #pragma unroll
            for (int e = 0; e < 4; e++) {
                float x = rp[e];
                ss = fmaf(x, x, ss);
                hb[e] = __half_as_ushort(__float2half_rn(x));
            }
            *(ushort4*)(g_Bh + (size_t)ci * DD + d0) =
                make_ushort4(hb[0], hb[1], hb[2], hb[3]);
        }
        #pragma unroll
        for (int o = 16; o; o >>= 1) ss += __shfl_xor_sync(0xFFFFFFFFu, ss, o);
        if (l == 0) g_invnorm[p] = 1.0f / (sqrtf(ss) + EPSF);
    }
    if (isq) {
        float ss = 0.f;
        #pragma unroll
        for (int g = 0; g < 4; g++) {
            int d0 = g * 128 + l * 4;
            int c = d0 >> 4, di = (d0 >> 2) & 3;
            const float* rp = high + c * HW + (pi + di) * WW + pj;
            unsigned short hb[4];
            #pragma unroll
            for (int e = 0; e < 4; e++) {
                float x = rp[e];
                ss = fmaf(x, x, ss);
                hb[e] = __half_as_ushort(__float2half_rn(x));
            }
            *(ushort4*)(g_Ah + (size_t)qi * DD + d0) =
                make_ushort4(hb[0], hb[1], hb[2], hb[3]);
        }
        #pragma unroll
        for (int o = 16; o; o >>= 1) ss += __shfl_xor_sync(0xFFFFFFFFu, ss, o);
        if (l == 0) g_margin[p] = 3.0f * ldexpf(sqrtf(ss), -10);
    }
}

// ---------------- K2: 1-pass fp16 GEMM, 32x64 tiles, persistent grid ---------
// 128 threads (4 warps: 2 m-warps x 2 n-halves); K chunked by 64, 2-stage pipe.
__global__ void __launch_bounds__(128, 5) gemm_h_kernel() {
    const int nq = g_qcount, nc = g_ccount;
    if (nq <= 0 || nc <= 0) return;
    const int qt = (nq + 31) >> 5, ct = (nc + 63) >> 6;
    const int ntiles = qt * ct;

    extern __shared__ __align__(1024) char smem[];
    float* cinv = (float*)(smem + SM_CINV);
    int*   qs   = (int*)(smem + SM_QS);
    const uint32_t sStage0 = smem_u32(smem + SM_BUF);

    const int tid = threadIdx.x;
    const int w   = tid >> 5;
    const int l   = tid & 31;
    const int mblk  = w >> 1;             // 0/1: row group of 16
    const int nhalf = w & 1;              // 0/1: col group of 32

    // copy roles
    const int arr = tid >> 2, aq = tid & 3;   // A: 32 rows, 4 thr/row, 32B each
    const int brr = tid >> 1, bh = tid & 1;   // B: 64 rows, 2 thr/row, 64B each
    // ldmatrix addressing
    const int arow = mblk * 16 + (l & 15);
    const int a_koff = (l >> 4);
    const int b_row8 = l & 7;
    const int b_koff = (l >> 3) & 1;
    const int b_nsel = (l >> 4) & 1;

    for (int t = blockIdx.x; t < ntiles; t += gridDim.x) {
        const int qb = t / ct, cb = t - qb * ct;
        __syncthreads();                  // protect header from prev tile readers
        if (tid < 64) {
            int ci = cb * 64 + tid;
            int co = (ci < nc) ? g_clist[ci] : 0;
            cinv[tid] = (ci < nc) ? g_invnorm[co] : 0.f;
        }
        if (tid < 32) {
            int qi2 = qb * 32 + tid;
            qs[tid] = (qi2 < nq) ? g_qlist[qi2] : -1;
        }

        int aro = qb * 32 + arr; if (aro > nq - 1) aro = nq - 1;
        int bro = cb * 64 + brr; if (bro > nc - 1) bro = nc - 1;
        const size_t aoff = (size_t)aro * (DD * 2);
        const size_t boff = (size_t)bro * (DD * 2);

        auto prefetch = [&](int s, int stage) {
            uint32_t bA = sStage0 + stage * STAGE_SZ;
            uint32_t bB = bA + BUFA_SZ;
            const char* srcA = (const char*)g_Ah + aoff + s * 128 + aq * 32;
            uint32_t dstA = bA + arr * 128;
            #pragma unroll
            for (int i = 0; i < 2; i++)
                cp16(dstA + (((aq * 2 + i) ^ (arr & 7)) * 16), srcA + i * 16);
            const char* srcB = (const char*)g_Bh + boff + s * 128 + bh * 64;
            uint32_t dstB = bB + brr * 128;
            #pragma unroll
            for (int i = 0; i < 4; i++)
                cp16(dstB + (((bh * 4 + i) ^ (brr & 7)) * 16), srcB + i * 16);
        };

        float acc[4][4];
        #pragma unroll
        for (int nb = 0; nb < 4; nb++)
            #pragma unroll
            for (int e = 0; e < 4; e++) acc[nb][e] = 0.f;

        prefetch(0, 0); CP_COMMIT();
        prefetch(1, 1); CP_COMMIT();

        for (int s = 0; s < 8; s++) {
            if (s < 7) { CP_WAIT1(); } else { CP_WAIT0(); }
            __syncthreads();
            const uint32_t sA = sStage0 + (s & 1) * STAGE_SZ;
            const uint32_t sB = sA + BUFA_SZ;
            #pragma unroll
            for (int kk = 0; kk < 4; kk++) {
                uint32_t af[4];
                {
                    int achunk = 2 * kk + a_koff;
                    uint32_t aaddr = sA + arow * 128 + ((achunk ^ (arow & 7)) * 16);
                    asm volatile("ldmatrix.sync.aligned.m8n8.x4.shared.b16 "
                                 "{%0,%1,%2,%3}, [%4];"
                                 : "=r"(af[0]), "=r"(af[1]), "=r"(af[2]), "=r"(af[3])
                                 : "r"(aaddr));
                }
                uint32_t bf[2][4];
                #pragma unroll
                for (int np2 = 0; np2 < 2; np2++) {
                    int brow2 = nhalf * 32 + (np2 * 2 + b_nsel) * 8 + b_row8;
                    int bchunk = 2 * kk + b_koff;
                    uint32_t baddr = sB + brow2 * 128 + ((bchunk ^ (brow2 & 7)) * 16);
                    asm volatile("ldmatrix.sync.aligned.m8n8.x4.shared.b16 "
                                 "{%0,%1,%2,%3}, [%4];"
                                 : "=r"(bf[np2][0]), "=r"(bf[np2][1]),
                                   "=r"(bf[np2][2]), "=r"(bf[np2][3])
                                 : "r"(baddr));
                }
                #pragma unroll
                for (int np2 = 0; np2 < 2; np2++) {
                    mma16816h(acc[np2 * 2 + 0], af, &bf[np2][0]);
                    mma16816h(acc[np2 * 2 + 1], af, &bf[np2][2]);
                }
            }
            __syncthreads();
            if (s + 2 < 8) { prefetch(s + 2, s & 1); CP_COMMIT(); }
        }

        // epilogue: store approx scores + per-query approx max
        int jmax = nc - cb * 64; if (jmax > 64) jmax = 64;
        #pragma unroll
        for (int h2 = 0; h2 < 2; h2++) {
            int rowm = mblk * 16 + (l >> 2) + h2 * 8;
            float* srow = g_scores + (size_t)(qb * 32 + rowm) * SCSTRIDE + cb * 64;
            float rmax = -3e38f;
            #pragma unroll
            for (int nb = 0; nb < 4; nb++) {
                #pragma unroll
                for (int e = 0; e < 2; e++) {
                    int nloc = nhalf * 32 + nb * 8 + (l & 3) * 2 + e;
                    float sc = acc[nb][h2 * 2 + e] * cinv[nloc];
                    srow[nloc] = sc;
                    if (nloc < jmax && sc > rmax) rmax = sc;
                }
            }
            rmax = fmaxf(rmax, __shfl_xor_sync(0xFFFFFFFFu, rmax, 1));
            rmax = fmaxf(rmax, __shfl_xor_sync(0xFFFFFFFFu, rmax, 2));
            if ((l & 3) == 0) {
                int qorig = qs[rowm];
                if (qorig >= 0) atomicMax(&g_qmax[qorig], mono(rmax));
            }
        }
    }
}

// ---------------- K3: exact fp32 rescore, one BLOCK per query ----------------
__global__ void __launch_bounds__(256) rescore_kernel(const float* __restrict__ low,
                                                      const float* __restrict__ high) {
    int qi = blockIdx.x;
    if (qi >= g_qcount) return;
    int l = threadIdx.x & 31, w = threadIdx.x >> 5;
    int nc = g_ccount;
    int qorig = g_qlist[qi];
    float thr = demono(g_qmax[qorig]) - g_margin[qorig];

    int qpi = qorig / HP, qpj = qorig % HP;
    float qv[16];
    #pragma unroll
    for (int tt = 0; tt < 16; tt++) {
        int d = tt * 32 + l;
        int c = d >> 4, di = (d >> 2) & 3, dj = d & 3;
        qv[tt] = high[c * HW + (qpi + di) * WW + (qpj + dj)];
    }

    unsigned long long best = 0ull;
    const float* srow = g_scores + (size_t)qi * SCSTRIDE;
    for (int ci0 = w * 32; ci0 < nc; ci0 += 256) {
        int ci = ci0 + l;
        float s = (ci < nc) ? srow[ci] : -3e38f;
        unsigned bal = __ballot_sync(0xFFFFFFFFu, s >= thr);
        while (bal) {
            int cj = __ffs(bal) - 1; bal &= bal - 1;
            int co = g_clist[ci0 + cj];
            int cpi = co / HP, cpj = co % HP;
            float dot = 0.f;
            #pragma unroll
            for (int tt = 0; tt < 16; tt++) {
                int d = tt * 32 + l;
                int c = d >> 4, di = (d >> 2) & 3, dj = d & 3;
                dot = fmaf(qv[tt], low[c * HW + (cpi + di) * WW + (cpj + dj)], dot);
            }
            #pragma unroll
            for (int o = 16; o; o >>= 1) dot += __shfl_xor_sync(0xFFFFFFFFu, dot, o);
            if (l == 0) {
                float sex = dot * g_invnorm[co];
                unsigned long long key =
                    ((unsigned long long)mono(sex) << 32) | (unsigned)(~co);
                if (key > best) best = key;
            }
        }
    }
    __shared__ unsigned long long s_best[8];
    if (l == 0) s_best[w] = best;
    __syncthreads();
    if (threadIdx.x == 0) {
        unsigned long long b = s_best[0];
        #pragma unroll
        for (int i = 1; i < 8; i++) if (s_best[i] > b) b = s_best[i];
        if (b != 0ull) g_keys[qorig] = b;
    }
}

// ---------------- K4: output assembly + counter reset for next replay --------
__global__ void output_kernel(const float* __restrict__ low,
                              float* __restrict__ out) {
    if (blockIdx.x == 0 && blockIdx.y == 0 && threadIdx.x == 0) {
        g_qcount = 0;                     // consumed only by next replay's prep
        g_ccount = 0;
    }
    int pix = blockIdx.x * blockDim.x + threadIdx.x;
    if (pix >= HW) return;
    int y = pix / WW, x = pix % WW;
    int c0 = blockIdx.y * 4;

    int   offr[16];
    bool  ok[16];
    float cnt = 0.f;
    #pragma unroll
    for (int t = 0; t < 16; t++) {
        int di = t >> 2, dj = t & 3;
        int i = y - di, j = x - dj;
        bool o = (i >= 0) && (i < HP) && (j >= 0) && (j < HP);
        int p = o ? (i * HP + j) : 0;
        o = o && g_valid[p];
        ok[t] = o;
        int off = 0;
        if (o) {
            unsigned bp = (unsigned)(~g_keys[p]);   // low 32 bits = ~best_cand
            int bi = bp / HP, bj = bp % HP;
            off = (bi + di) * WW + (bj + dj);
            cnt += 1.f;
        }
        offr[t] = off;
    }

    if (cnt == 0.f) {
        #pragma unroll
        for (int c = 0; c < 4; c++)
            out[(c0 + c) * HW + pix] = low[(c0 + c) * HW + pix];
        return;
    }
    float inv = 1.f / (cnt + EPSF);
    #pragma unroll
    for (int c = 0; c < 4; c++) {
        const float* lc = low + (c0 + c) * HW;
        float a = 0.f;
        #pragma unroll
        for (int t = 0; t < 16; t++)
            if (ok[t]) a += lc[offr[t]];
        out[(c0 + c) * HW + pix] = a * inv;
    }
}

// ---------------- launcher ---------------------------------------------------
extern "C" void kernel_launch(void* const* d_in, const int* in_sizes, int n_in,
                              void* d_out, int out_size) {
    const float* low  = (const float*)d_in[0];
    const float* high = (const float*)d_in[1];
    const int*   mask = (const int*)d_in[2];
    float*       out  = (float*)d_out;

    cudaFuncSetAttribute(gemm_h_kernel,
                         cudaFuncAttributeMaxDynamicSharedMemorySize, SMEM_TOTAL);

    prep_kernel<<<(NP * 32 + 255) / 256, 256>>>(low, high, mask);
    gemm_h_kernel<<<740, 128, SMEM_TOTAL>>>();
    rescore_kernel<<<NP, 256>>>(low, high);
    output_kernel<<<dim3((HW + 255) / 256, 8), 256>>>(low, out);
}

// round 12
// speedup vs baseline: 1.3636x; 1.3636x over previous
#include <cuda_runtime.h>
#include <cuda_fp16.h>
#include <cstdint>

// Problem constants
#define CC   32
#define HH   80
#define WW   80
#define KK   4
#define HP   77            // HH-KK+1
#define NP   (HP*HP)       // 5929 patches
#define DD   (CC*KK*KK)    // 512
#define MW   81            // mask width (H+1)
#define EPSF 1e-6f
#define HW   (HH*WW)
#define SCSTRIDE 6016      // padded candidate stride
#define SCROWS   6016      // padded query rows

// ---------------- device scratch (allocation-free rule) ----------------------
__device__ __align__(16) __half g_Ah[NP * DD];   // compacted queries (high), fp16
__device__ __align__(16) __half g_Bh[NP * DD];   // compacted candidates (low), fp16
__device__ float              g_scores[(size_t)SCROWS * SCSTRIDE]; // approx scores
__device__ float              g_invnorm[NP];
__device__ float              g_margin[NP];       // 3 * 2^-10 * ||q_p||
__device__ unsigned           g_qmax[NP];         // mono(approx max) per query patch
__device__ unsigned char      g_valid[NP];
__device__ unsigned long long g_keys[NP];
__device__ int                g_delta[NP];        // best-match pixel offset delta
__device__ int                g_qlist[NP];
__device__ int                g_clist[NP];
__device__ int                g_qcount;           // zero-init at load; reset by output
__device__ int                g_ccount;

// ---------------- helpers -----------------------------------------------------
__device__ __forceinline__ unsigned mono(float f) {
    unsigned b = __float_as_uint(f);
    return (b & 0x80000000u) ? ~b : (b | 0x80000000u);
}
__device__ __forceinline__ float demono(unsigned u) {
    unsigned b = (u & 0x80000000u) ? (u & 0x7FFFFFFFu) : ~u;
    return __uint_as_float(b);
}
__device__ __forceinline__ uint32_t smem_u32(const void* p) {
    uint32_t a;
    asm("{ .reg .u64 t; cvta.to.shared.u64 t, %1; cvt.u32.u64 %0, t; }"
        : "=r"(a) : "l"(p));
    return a;
}
__device__ __forceinline__ void mma16816h(float* c, const uint32_t* a, const uint32_t* b) {
    asm volatile(
        "mma.sync.aligned.m16n8k16.row.col.f32.f16.f16.f32 "
        "{%0,%1,%2,%3}, {%4,%5,%6,%7}, {%8,%9}, {%0,%1,%2,%3};"
        : "+f"(c[0]), "+f"(c[1]), "+f"(c[2]), "+f"(c[3])
        : "r"(a[0]), "r"(a[1]), "r"(a[2]), "r"(a[3]), "r"(b[0]), "r"(b[1]));
}
__device__ __forceinline__ void cp16(uint32_t dst, const void* src) {
    asm volatile("cp.async.cg.shared.global [%0], [%1], 16;" :: "r"(dst), "l"(src));
}
#define CP_COMMIT() asm volatile("cp.async.commit_group;" ::: "memory")
#define CP_WAIT1()  asm volatile("cp.async.wait_group 1;" ::: "memory")
#define CP_WAIT0()  asm volatile("cp.async.wait_group 0;" ::: "memory")

// smem layout for the GEMM kernel (dynamic)
#define SM_CINV   0          // 64 floats
#define SM_QS     256        // 32 ints
#define SM_BUF    1024
#define BUFA_SZ   4096       // 32 rows x 128B (64 fp16)
#define BUFB_SZ   8192       // 64 rows x 128B
#define STAGE_SZ  (BUFA_SZ + BUFB_SZ)           // 12288
#define SMEM_TOTAL (SM_BUF + 2 * STAGE_SZ)      // 25600

// ---------------- K1: fused prep — warp per patch ----------------------------
// mask flags + compaction + fp16 gather + norms, all in one pass.
__global__ void __launch_bounds__(256) prep_kernel(const float* __restrict__ low,
                                                   const float* __restrict__ high,
                                                   const int* __restrict__ mask) {
    int p = (blockIdx.x * blockDim.x + threadIdx.x) >> 5;
    int l = threadIdx.x & 31;
    if (p >= NP) return;
    int pi = p / HP, pj = p % HP;

    int m00 = mask[pi * MW + pj];
    int m01 = mask[pi * MW + pj + KK];
    int m10 = mask[(pi + KK) * MW + pj];
    int m11 = mask[(pi + KK) * MW + pj + KK];
    bool iscand = (m00 != 1);
    bool isq    = (m00 != 0) && (m01 != 0) && (m10 != 0) && (m11 != 0);

    int ci = 0, qi = 0;
    if (l == 0) {
        g_keys[p]  = ((unsigned long long)mono(-1e9f) << 32) | 0xFFFFFFFFull;
        g_valid[p] = (unsigned char)isq;
        g_qmax[p]  = 0u;
        g_delta[p] = -pi * WW - pj;       // fallback: candidate 0
        if (iscand) { ci = atomicAdd(&g_ccount, 1); g_clist[ci] = p; }
        if (isq)    { qi = atomicAdd(&g_qcount, 1); g_qlist[qi] = p; }
    }
    ci = __shfl_sync(0xFFFFFFFFu, ci, 0);
    qi = __shfl_sync(0xFFFFFFFFu, qi, 0);

    if (iscand) {
        float ss = 0.f;
        #pragma unroll
        for (int g = 0; g < 4; g++) {
            int d0 = g * 128 + l * 4;              // 4 consecutive elems, dj=0..3
            int c = d0 >> 4, di = (d0 >> 2) & 3;
            const float* rp = low + c * HW + (pi + di) * WW + pj;
            unsigned short hb[4];
            #pragma unroll
            for (int e = 0; e < 4; e++) {
                float x = rp[e];
                ss = fmaf(x, x, ss);
                hb[e] = __half_as_ushort(__float2half_rn(x));
            }
            *(ushort4*)(g_Bh + (size_t)ci * DD + d0) =
                make_ushort4(hb[0], hb[1], hb[2], hb[3]);
        }
        #pragma unroll
        for (int o = 16; o; o >>= 1) ss += __shfl_xor_sync(0xFFFFFFFFu, ss, o);
        if (l == 0) g_invnorm[p] = 1.0f / (sqrtf(ss) + EPSF);
    }
    if (isq) {
        float ss = 0.f;
        #pragma unroll
        for (int g = 0; g < 4; g++) {
            int d0 = g * 128 + l * 4;
            int c = d0 >> 4, di = (d0 >> 2) & 3;
            const float* rp = high + c * HW + (pi + di) * WW + pj;
            unsigned short hb[4];
            #pragma unroll
            for (int e = 0; e < 4; e++) {
                float x = rp[e];
                ss = fmaf(x, x, ss);
                hb[e] = __half_as_ushort(__float2half_rn(x));
            }
            *(ushort4*)(g_Ah + (size_t)qi * DD + d0) =
                make_ushort4(hb[0], hb[1], hb[2], hb[3]);
        }
        #pragma unroll
        for (int o = 16; o; o >>= 1) ss += __shfl_xor_sync(0xFFFFFFFFu, ss, o);
        if (l == 0) g_margin[p] = 3.0f * ldexpf(sqrtf(ss), -10);
    }
}

// ---------------- K2: 1-pass fp16 GEMM, 32x64 tiles, persistent grid ---------
// 128 threads (4 warps: 2 m-warps x 2 n-halves); K chunked by 64, 2-stage pipe.
__global__ void __launch_bounds__(128, 4) gemm_h_kernel() {
    const int nq = g_qcount, nc = g_ccount;
    if (nq <= 0 || nc <= 0) return;
    const int qt = (nq + 31) >> 5, ct = (nc + 63) >> 6;
    const int ntiles = qt * ct;

    extern __shared__ __align__(1024) char smem[];
    float* cinv = (float*)(smem + SM_CINV);
    int*   qs   = (int*)(smem + SM_QS);
    const uint32_t sStage0 = smem_u32(smem + SM_BUF);

    const int tid = threadIdx.x;
    const int w   = tid >> 5;
    const int l   = tid & 31;
    const int mblk  = w >> 1;             // 0/1: row group of 16
    const int nhalf = w & 1;              // 0/1: col group of 32

    // copy roles
    const int arr = tid >> 2, aq = tid & 3;   // A: 32 rows, 4 thr/row, 32B each
    const int brr = tid >> 1, bh = tid & 1;   // B: 64 rows, 2 thr/row, 64B each
    // ldmatrix addressing
    const int arow = mblk * 16 + (l & 15);
    const int a_koff = (l >> 4);
    const int b_row8 = l & 7;
    const int b_koff = (l >> 3) & 1;
    const int b_nsel = (l >> 4) & 1;

    for (int t = blockIdx.x; t < ntiles; t += gridDim.x) {
        const int qb = t / ct, cb = t - qb * ct;
        __syncthreads();                  // protect header from prev tile readers
        if (tid < 64) {
            int ci = cb * 64 + tid;
            int co = (ci < nc) ? g_clist[ci] : 0;
            cinv[tid] = (ci < nc) ? g_invnorm[co] : 0.f;
        }
        if (tid < 32) {
            int qi2 = qb * 32 + tid;
            qs[tid] = (qi2 < nq) ? g_qlist[qi2] : -1;
        }

        int aro = qb * 32 + arr; if (aro > nq - 1) aro = nq - 1;
        int bro = cb * 64 + brr; if (bro > nc - 1) bro = nc - 1;
        const size_t aoff = (size_t)aro * (DD * 2);
        const size_t boff = (size_t)bro * (DD * 2);

        auto prefetch = [&](int s, int stage) {
            uint32_t bA = sStage0 + stage * STAGE_SZ;
            uint32_t bB = bA + BUFA_SZ;
            const char* srcA = (const char*)g_Ah + aoff + s * 128 + aq * 32;
            uint32_t dstA = bA + arr * 128;
            #pragma unroll
            for (int i = 0; i < 2; i++)
                cp16(dstA + (((aq * 2 + i) ^ (arr & 7)) * 16), srcA + i * 16);
            const char* srcB = (const char*)g_Bh + boff + s * 128 + bh * 64;
            uint32_t dstB = bB + brr * 128;
            #pragma unroll
            for (int i = 0; i < 4; i++)
                cp16(dstB + (((bh * 4 + i) ^ (brr & 7)) * 16), srcB + i * 16);
        };

        float acc[4][4];
        #pragma unroll
        for (int nb = 0; nb < 4; nb++)
            #pragma unroll
            for (int e = 0; e < 4; e++) acc[nb][e] = 0.f;

        prefetch(0, 0); CP_COMMIT();
        prefetch(1, 1); CP_COMMIT();

        for (int s = 0; s < 8; s++) {
            if (s < 7) { CP_WAIT1(); } else { CP_WAIT0(); }
            __syncthreads();
            const uint32_t sA = sStage0 + (s & 1) * STAGE_SZ;
            const uint32_t sB = sA + BUFA_SZ;
            #pragma unroll
            for (int kk = 0; kk < 4; kk++) {
                uint32_t af[4];
                {
                    int achunk = 2 * kk + a_koff;
                    uint32_t aaddr = sA + arow * 128 + ((achunk ^ (arow & 7)) * 16);
                    asm volatile("ldmatrix.sync.aligned.m8n8.x4.shared.b16 "
                                 "{%0,%1,%2,%3}, [%4];"
                                 : "=r"(af[0]), "=r"(af[1]), "=r"(af[2]), "=r"(af[3])
                                 : "r"(aaddr));
                }
                uint32_t bf[2][4];
                #pragma unroll
                for (int np2 = 0; np2 < 2; np2++) {
                    int brow2 = nhalf * 32 + (np2 * 2 + b_nsel) * 8 + b_row8;
                    int bchunk = 2 * kk + b_koff;
                    uint32_t baddr = sB + brow2 * 128 + ((bchunk ^ (brow2 & 7)) * 16);
                    asm volatile("ldmatrix.sync.aligned.m8n8.x4.shared.b16 "
                                 "{%0,%1,%2,%3}, [%4];"
                                 : "=r"(bf[np2][0]), "=r"(bf[np2][1]),
                                   "=r"(bf[np2][2]), "=r"(bf[np2][3])
                                 : "r"(baddr));
                }
                #pragma unroll
                for (int np2 = 0; np2 < 2; np2++) {
                    mma16816h(acc[np2 * 2 + 0], af, &bf[np2][0]);
                    mma16816h(acc[np2 * 2 + 1], af, &bf[np2][2]);
                }
            }
            __syncthreads();
            if (s + 2 < 8) { prefetch(s + 2, s & 1); CP_COMMIT(); }
        }

        // epilogue: store approx scores + per-query approx max
        int jmax = nc - cb * 64; if (jmax > 64) jmax = 64;
        #pragma unroll
        for (int h2 = 0; h2 < 2; h2++) {
            int rowm = mblk * 16 + (l >> 2) + h2 * 8;
            float* srow = g_scores + (size_t)(qb * 32 + rowm) * SCSTRIDE + cb * 64;
            float rmax = -3e38f;
            #pragma unroll
            for (int nb = 0; nb < 4; nb++) {
                #pragma unroll
                for (int e = 0; e < 2; e++) {
                    int nloc = nhalf * 32 + nb * 8 + (l & 3) * 2 + e;
                    float sc = acc[nb][h2 * 2 + e] * cinv[nloc];
                    srow[nloc] = sc;
                    if (nloc < jmax && sc > rmax) rmax = sc;
                }
            }
            rmax = fmaxf(rmax, __shfl_xor_sync(0xFFFFFFFFu, rmax, 1));
            rmax = fmaxf(rmax, __shfl_xor_sync(0xFFFFFFFFu, rmax, 2));
            if ((l & 3) == 0) {
                int qorig = qs[rowm];
                if (qorig >= 0) atomicMax(&g_qmax[qorig], mono(rmax));
            }
        }
    }
}

// ---------------- K3: exact fp32 rescore, one BLOCK per query ----------------
// Also writes the decoded best-match delta for the output kernel.
__global__ void __launch_bounds__(256) rescore_kernel(const float* __restrict__ low,
                                                      const float* __restrict__ high) {
    int qi = blockIdx.x;
    if (qi >= g_qcount) return;
    int l = threadIdx.x & 31, w = threadIdx.x >> 5;
    int nc = g_ccount;
    int qorig = g_qlist[qi];
    float thr = demono(g_qmax[qorig]) - g_margin[qorig];

    int qpi = qorig / HP, qpj = qorig % HP;
    float qv[16];
    #pragma unroll
    for (int tt = 0; tt < 16; tt++) {
        int d = tt * 32 + l;
        int c = d >> 4, di = (d >> 2) & 3, dj = d & 3;
        qv[tt] = high[c * HW + (qpi + di) * WW + (qpj + dj)];
    }

    unsigned long long best = 0ull;
    const float* srow = g_scores + (size_t)qi * SCSTRIDE;
    for (int ci0 = w * 32; ci0 < nc; ci0 += 256) {
        int ci = ci0 + l;
        float s = (ci < nc) ? srow[ci] : -3e38f;
        unsigned bal = __ballot_sync(0xFFFFFFFFu, s >= thr);
        while (bal) {
            int cj = __ffs(bal) - 1; bal &= bal - 1;
            int co = g_clist[ci0 + cj];
            int cpi = co / HP, cpj = co % HP;
            float dot = 0.f;
            #pragma unroll
            for (int tt = 0; tt < 16; tt++) {
                int d = tt * 32 + l;
                int c = d >> 4, di = (d >> 2) & 3, dj = d & 3;
                dot = fmaf(qv[tt], low[c * HW + (cpi + di) * WW + (cpj + dj)], dot);
            }
            #pragma unroll
            for (int o = 16; o; o >>= 1) dot += __shfl_xor_sync(0xFFFFFFFFu, dot, o);
            if (l == 0) {
                float sex = dot * g_invnorm[co];
                unsigned long long key =
                    ((unsigned long long)mono(sex) << 32) | (unsigned)(~co);
                if (key > best) best = key;
            }
        }
    }
    __shared__ unsigned long long s_best[8];
    if (l == 0) s_best[w] = best;
    __syncthreads();
    if (threadIdx.x == 0) {
        unsigned long long b = s_best[0];
        #pragma unroll
        for (int i = 1; i < 8; i++) if (s_best[i] > b) b = s_best[i];
        if (b != 0ull) {
            g_keys[qorig] = b;
            unsigned bp = (unsigned)(~b);           // low 32 bits = ~best cand
            int bi = bp / HP, bj = bp % HP;
            g_delta[qorig] = (bi - qpi) * WW + (bj - qpj);
        }
        // else keep prep's fallback delta (candidate 0)
    }
}

// ---------------- K4: output assembly (delta-based) + counter reset ----------
__global__ void __launch_bounds__(128) output_kernel(const float* __restrict__ low,
                                                     float* __restrict__ out) {
    if (blockIdx.x == 0 && blockIdx.y == 0 && threadIdx.x == 0) {
        g_qcount = 0;                     // consumed only by next replay's prep
        g_ccount = 0;
    }
    int pix = blockIdx.x * blockDim.x + threadIdx.x;
    if (pix >= HW) return;
    int y = pix / WW, x = pix % WW;
    int c0 = blockIdx.y * 4;

    int   offr[16];
    bool  ok[16];
    float cnt = 0.f;
    #pragma unroll
    for (int t = 0; t < 16; t++) {
        int di = t >> 2, dj = t & 3;
        int i = y - di, j = x - dj;
        bool o = (i >= 0) && (i < HP) && (j >= 0) && (j < HP);
        int p = o ? (i * HP + j) : 0;
        o = o && g_valid[p];
        ok[t] = o;
        offr[t] = o ? (pix + g_delta[p]) : 0;
        if (o) cnt += 1.f;
    }

    if (cnt == 0.f) {
        #pragma unroll
        for (int c = 0; c < 4; c++)
            out[(c0 + c) * HW + pix] = low[(c0 + c) * HW + pix];
        return;
    }
    float inv = 1.f / (cnt + EPSF);
    #pragma unroll
    for (int c = 0; c < 4; c++) {
        const float* lc = low + (c0 + c) * HW;
        float a = 0.f;
        #pragma unroll
        for (int t = 0; t < 16; t++)
            if (ok[t]) a += lc[offr[t]];
        out[(c0 + c) * HW + pix] = a * inv;
    }
}

// ---------------- launcher ---------------------------------------------------
extern "C" void kernel_launch(void* const* d_in, const int* in_sizes, int n_in,
                              void* d_out, int out_size) {
    const float* low  = (const float*)d_in[0];
    const float* high = (const float*)d_in[1];
    const int*   mask = (const int*)d_in[2];
    float*       out  = (float*)d_out;

    cudaFuncSetAttribute(gemm_h_kernel,
                         cudaFuncAttributeMaxDynamicSharedMemorySize, SMEM_TOTAL);

    prep_kernel<<<(NP * 32 + 255) / 256, 256>>>(low, high, mask);
    gemm_h_kernel<<<592, 128, SMEM_TOTAL>>>();
    rescore_kernel<<<NP, 256>>>(low, high);
    output_kernel<<<dim3((HW + 127) / 128, 8), 128>>>(low, out);
}

// round 16
// speedup vs baseline: 1.3782x; 1.0107x over previous
#include <cuda_runtime.h>
#include <cuda_fp16.h>
#include <cstdint>

// Problem constants
#define CC   32
#define HH   80
#define WW   80
#define KK   4
#define HP   77            // HH-KK+1
#define NP   (HP*HP)       // 5929 patches
#define DD   (CC*KK*KK)    // 512
#define MW   81            // mask width (H+1)
#define EPSF 1e-6f
#define HW   (HH*WW)
#define SCSTRIDE 6016      // padded candidate stride
#define SCROWS   6016      // padded query rows

// ---------------- device scratch (allocation-free rule) ----------------------
__device__ __align__(16) __half g_Ah[NP * DD];   // compacted queries (high), fp16
__device__ __align__(16) __half g_Bh[NP * DD];   // compacted candidates (low), fp16
__device__ float              g_scores[(size_t)SCROWS * SCSTRIDE]; // approx scores
__device__ float              g_invnorm[NP];
__device__ float              g_margin[NP];       // 3 * 2^-10 * ||q_p||
__device__ unsigned           g_qmax[NP];         // mono(approx max) per query patch
__device__ unsigned char      g_valid[NP];
__device__ unsigned long long g_keys[NP];
__device__ int                g_delta[NP];        // best-match pixel offset delta
__device__ int                g_qlist[NP];
__device__ int                g_clist[NP];
__device__ int                g_qcount;           // zero-init at load; reset by output
__device__ int                g_ccount;

// ---------------- helpers -----------------------------------------------------
__device__ __forceinline__ unsigned mono(float f) {
    unsigned b = __float_as_uint(f);
    return (b & 0x80000000u) ? ~b : (b | 0x80000000u);
}
__device__ __forceinline__ float demono(unsigned u) {
    unsigned b = (u & 0x80000000u) ? (u & 0x7FFFFFFFu) : ~u;
    return __uint_as_float(b);
}
__device__ __forceinline__ uint32_t smem_u32(const void* p) {
    uint32_t a;
    asm("{ .reg .u64 t; cvta.to.shared.u64 t, %1; cvt.u32.u64 %0, t; }"
        : "=r"(a) : "l"(p));
    return a;
}
__device__ __forceinline__ void mma16816h(float* c, const uint32_t* a, const uint32_t* b) {
    asm volatile(
        "mma.sync.aligned.m16n8k16.row.col.f32.f16.f16.f32 "
        "{%0,%1,%2,%3}, {%4,%5,%6,%7}, {%8,%9}, {%0,%1,%2,%3};"
        : "+f"(c[0]), "+f"(c[1]), "+f"(c[2]), "+f"(c[3])
        : "r"(a[0]), "r"(a[1]), "r"(a[2]), "r"(a[3]), "r"(b[0]), "r"(b[1]));
}
__device__ __forceinline__ void cp16(uint32_t dst, const void* src) {
    asm volatile("cp.async.cg.shared.global [%0], [%1], 16;" :: "r"(dst), "l"(src));
}
#define CP_COMMIT() asm volatile("cp.async.commit_group;" ::: "memory")
#define CP_WAIT2()  asm volatile("cp.async.wait_group 2;" ::: "memory")
#define CP_WAIT1()  asm volatile("cp.async.wait_group 1;" ::: "memory")
#define CP_WAIT0()  asm volatile("cp.async.wait_group 0;" ::: "memory")

// smem layout for the GEMM kernel (dynamic) — 3-stage pipeline
#define SM_CINV   0          // 64 floats
#define SM_QS     256        // 32 ints
#define SM_BUF    1024
#define BUFA_SZ   4096       // 32 rows x 128B (64 fp16)
#define BUFB_SZ   8192       // 64 rows x 128B
#define STAGE_SZ  (BUFA_SZ + BUFB_SZ)           // 12288
#define NSTAGE    3
#define SMEM_TOTAL (SM_BUF + NSTAGE * STAGE_SZ) // 37888

// ---------------- K1: fused prep — warp per patch ----------------------------
__global__ void __launch_bounds__(256) prep_kernel(const float* __restrict__ low,
                                                   const float* __restrict__ high,
                                                   const int* __restrict__ mask) {
    int p = (blockIdx.x * blockDim.x + threadIdx.x) >> 5;
    int l = threadIdx.x & 31;
    if (p >= NP) return;
    int pi = p / HP, pj = p % HP;

    int m00 = mask[pi * MW + pj];
    int m01 = mask[pi * MW + pj + KK];
    int m10 = mask[(pi + KK) * MW + pj];
    int m11 = mask[(pi + KK) * MW + pj + KK];
    bool iscand = (m00 != 1);
    bool isq    = (m00 != 0) && (m01 != 0) && (m10 != 0) && (m11 != 0);

    int ci = 0, qi = 0;
    if (l == 0) {
        g_keys[p]  = ((unsigned long long)mono(-1e9f) << 32) | 0xFFFFFFFFull;
        g_valid[p] = (unsigned char)isq;
        g_qmax[p]  = 0u;
        g_delta[p] = -pi * WW - pj;       // fallback: candidate 0
        if (iscand) { ci = atomicAdd(&g_ccount, 1); g_clist[ci] = p; }
        if (isq)    { qi = atomicAdd(&g_qcount, 1); g_qlist[qi] = p; }
    }
    ci = __shfl_sync(0xFFFFFFFFu, ci, 0);
    qi = __shfl_sync(0xFFFFFFFFu, qi, 0);

    if (iscand) {
        float ss = 0.f;
        #pragma unroll
        for (int g = 0; g < 4; g++) {
            int d0 = g * 128 + l * 4;              // 4 consecutive elems, dj=0..3
            int c = d0 >> 4, di = (d0 >> 2) & 3;
            const float* rp = low + c * HW + (pi + di) * WW + pj;
            unsigned short hb[4];
            #pragma unroll
            for (int e = 0; e < 4; e++) {
                float x = rp[e];
                ss = fmaf(x, x, ss);
                hb[e] = __half_as_ushort(__float2half_rn(x));
            }
            *(ushort4*)(g_Bh + (size_t)ci * DD + d0) =
                make_ushort4(hb[0], hb[1], hb[2], hb[3]);
        }
        #pragma unroll
        for (int o = 16; o; o >>= 1) ss += __shfl_xor_sync(0xFFFFFFFFu, ss, o);
        if (l == 0) g_invnorm[p] = 1.0f / (sqrtf(ss) + EPSF);
    }
    if (isq) {
        float ss = 0.f;
        #pragma unroll
        for (int g = 0; g < 4; g++) {
            int d0 = g * 128 + l * 4;
            int c = d0 >> 4, di = (d0 >> 2) & 3;
            const float* rp = high + c * HW + (pi + di) * WW + pj;
            unsigned short hb[4];
            #pragma unroll
            for (int e = 0; e < 4; e++) {
                float x = rp[e];
                ss = fmaf(x, x, ss);
                hb[e] = __half_as_ushort(__float2half_rn(x));
            }
            *(ushort4*)(g_Ah + (size_t)qi * DD + d0) =
                make_ushort4(hb[0], hb[1], hb[2], hb[3]);
        }
        #pragma unroll
        for (int o = 16; o; o >>= 1) ss += __shfl_xor_sync(0xFFFFFFFFu, ss, o);
        if (l == 0) g_margin[p] = 3.0f * ldexpf(sqrtf(ss), -10);
    }
}

// ---------------- K2: 1-pass fp16 GEMM, 32x64 tiles, 3-stage pipeline --------
// 128 threads (4 warps: 2 m-warps x 2 n-halves); K chunked by 64.
__global__ void __launch_bounds__(128, 4) gemm_h_kernel() {
    const int nq = g_qcount, nc = g_ccount;
    if (nq <= 0 || nc <= 0) return;
    const int qt = (nq + 31) >> 5, ct = (nc + 63) >> 6;
    const int ntiles = qt * ct;

    extern __shared__ __align__(1024) char smem[];
    float* cinv = (float*)(smem + SM_CINV);
    int*   qs   = (int*)(smem + SM_QS);
    const uint32_t sStage0 = smem_u32(smem + SM_BUF);

    const int tid = threadIdx.x;
    const int w   = tid >> 5;
    const int l   = tid & 31;
    const int mblk  = w >> 1;             // 0/1: row group of 16
    const int nhalf = w & 1;              // 0/1: col group of 32

    // copy roles
    const int arr = tid >> 2, aq = tid & 3;   // A: 32 rows, 4 thr/row, 32B each
    const int brr = tid >> 1, bh = tid & 1;   // B: 64 rows, 2 thr/row, 64B each
    // ldmatrix addressing
    const int arow = mblk * 16 + (l & 15);
    const int a_koff = (l >> 4);
    const int b_row8 = l & 7;
    const int b_koff = (l >> 3) & 1;
    const int b_nsel = (l >> 4) & 1;

    for (int t = blockIdx.x; t < ntiles; t += gridDim.x) {
        const int qb = t / ct, cb = t - qb * ct;
        __syncthreads();                  // protect header from prev tile readers
        if (tid < 64) {
            int ci = cb * 64 + tid;
            int co = (ci < nc) ? g_clist[ci] : 0;
            cinv[tid] = (ci < nc) ? g_invnorm[co] : 0.f;
        }
        if (tid < 32) {
            int qi2 = qb * 32 + tid;
            qs[tid] = (qi2 < nq) ? g_qlist[qi2] : -1;
        }

        int aro = qb * 32 + arr; if (aro > nq - 1) aro = nq - 1;
        int bro = cb * 64 + brr; if (bro > nc - 1) bro = nc - 1;
        const size_t aoff = (size_t)aro * (DD * 2);
        const size_t boff = (size_t)bro * (DD * 2);

        auto prefetch = [&](int s, int stage) {
            uint32_t bA = sStage0 + stage * STAGE_SZ;
            uint32_t bB = bA + BUFA_SZ;
            const char* srcA = (const char*)g_Ah + aoff + s * 128 + aq * 32;
            uint32_t dstA = bA + arr * 128;
            #pragma unroll
            for (int i = 0; i < 2; i++)
                cp16(dstA + (((aq * 2 + i) ^ (arr & 7)) * 16), srcA + i * 16);
            const char* srcB = (const char*)g_Bh + boff + s * 128 + bh * 64;
            uint32_t dstB = bB + brr * 128;
            #pragma unroll
            for (int i = 0; i < 4; i++)
                cp16(dstB + (((bh * 4 + i) ^ (brr & 7)) * 16), srcB + i * 16);
        };

        float acc[4][4];
        #pragma unroll
        for (int nb = 0; nb < 4; nb++)
            #pragma unroll
            for (int e = 0; e < 4; e++) acc[nb][e] = 0.f;

        prefetch(0, 0); CP_COMMIT();
        prefetch(1, 1); CP_COMMIT();
        prefetch(2, 2); CP_COMMIT();

        for (int s = 0; s < 8; s++) {
            if (s < 6)      { CP_WAIT2(); }
            else if (s == 6){ CP_WAIT1(); }
            else            { CP_WAIT0(); }
            __syncthreads();
            const int st = s % NSTAGE;
            const uint32_t sA = sStage0 + st * STAGE_SZ;
            const uint32_t sB = sA + BUFA_SZ;
            #pragma unroll
            for (int kk = 0; kk < 4; kk++) {
                uint32_t af[4];
                {
                    int achunk = 2 * kk + a_koff;
                    uint32_t aaddr = sA + arow * 128 + ((achunk ^ (arow & 7)) * 16);
                    asm volatile("ldmatrix.sync.aligned.m8n8.x4.shared.b16 "
                                 "{%0,%1,%2,%3}, [%4];"
                                 : "=r"(af[0]), "=r"(af[1]), "=r"(af[2]), "=r"(af[3])
                                 : "r"(aaddr));
                }
                uint32_t bf[2][4];
                #pragma unroll
                for (int np2 = 0; np2 < 2; np2++) {
                    int brow2 = nhalf * 32 + (np2 * 2 + b_nsel) * 8 + b_row8;
                    int bchunk = 2 * kk + b_koff;
                    uint32_t baddr = sB + brow2 * 128 + ((bchunk ^ (brow2 & 7)) * 16);
                    asm volatile("ldmatrix.sync.aligned.m8n8.x4.shared.b16 "
                                 "{%0,%1,%2,%3}, [%4];"
                                 : "=r"(bf[np2][0]), "=r"(bf[np2][1]),
                                   "=r"(bf[np2][2]), "=r"(bf[np2][3])
                                 : "r"(baddr));
                }
                #pragma unroll
                for (int np2 = 0; np2 < 2; np2++) {
                    mma16816h(acc[np2 * 2 + 0], af, &bf[np2][0]);
                    mma16816h(acc[np2 * 2 + 1], af, &bf[np2][2]);
                }
            }
            __syncthreads();
            if (s + 3 < 8) { prefetch(s + 3, st); CP_COMMIT(); }
        }

        // epilogue: store approx scores + per-query approx max
        int jmax = nc - cb * 64; if (jmax > 64) jmax = 64;
        #pragma unroll
        for (int h2 = 0; h2 < 2; h2++) {
            int rowm = mblk * 16 + (l >> 2) + h2 * 8;
            float* srow = g_scores + (size_t)(qb * 32 + rowm) * SCSTRIDE + cb * 64;
            float rmax = -3e38f;
            #pragma unroll
            for (int nb = 0; nb < 4; nb++) {
                #pragma unroll
                for (int e = 0; e < 2; e++) {
                    int nloc = nhalf * 32 + nb * 8 + (l & 3) * 2 + e;
                    float sc = acc[nb][h2 * 2 + e] * cinv[nloc];
                    srow[nloc] = sc;
                    if (nloc < jmax && sc > rmax) rmax = sc;
                }
            }
            rmax = fmaxf(rmax, __shfl_xor_sync(0xFFFFFFFFu, rmax, 1));
            rmax = fmaxf(rmax, __shfl_xor_sync(0xFFFFFFFFu, rmax, 2));
            if ((l & 3) == 0) {
                int qorig = qs[rowm];
                if (qorig >= 0) atomicMax(&g_qmax[qorig], mono(rmax));
            }
        }
    }
}

// ---------------- K3: exact fp32 rescore, one BLOCK per query ----------------
__global__ void __launch_bounds__(256) rescore_kernel(const float* __restrict__ low,
                                                      const float* __restrict__ high) {
    int qi = blockIdx.x;
    if (qi >= g_qcount) return;
    int l = threadIdx.x & 31, w = threadIdx.x >> 5;
    int nc = g_ccount;
    int qorig = g_qlist[qi];
    float thr = demono(g_qmax[qorig]) - g_margin[qorig];

    int qpi = qorig / HP, qpj = qorig % HP;
    float qv[16];
    #pragma unroll
    for (int tt = 0; tt < 16; tt++) {
        int d = tt * 32 + l;
        int c = d >> 4, di = (d >> 2) & 3, dj = d & 3;
        qv[tt] = high[c * HW + (qpi + di) * WW + (qpj + dj)];
    }

    unsigned long long best = 0ull;
    const float* srow = g_scores + (size_t)qi * SCSTRIDE;
    for (int ci0 = w * 32; ci0 < nc; ci0 += 256) {
        int ci = ci0 + l;
        float s = (ci < nc) ? srow[ci] : -3e38f;
        unsigned bal = __ballot_sync(0xFFFFFFFFu, s >= thr);
        while (bal) {
            int cj = __ffs(bal) - 1; bal &= bal - 1;
            int co = g_clist[ci0 + cj];
            int cpi = co / HP, cpj = co % HP;
            float dot = 0.f;
            #pragma unroll
            for (int tt = 0; tt < 16; tt++) {
                int d = tt * 32 + l;
                int c = d >> 4, di = (d >> 2) & 3, dj = d & 3;
                dot = fmaf(qv[tt], low[c * HW + (cpi + di) * WW + (cpj + dj)], dot);
            }
            #pragma unroll
            for (int o = 16; o; o >>= 1) dot += __shfl_xor_sync(0xFFFFFFFFu, dot, o);
            if (l == 0) {
                float sex = dot * g_invnorm[co];
                unsigned long long key =
                    ((unsigned long long)mono(sex) << 32) | (unsigned)(~co);
                if (key > best) best = key;
            }
        }
    }
    __shared__ unsigned long long s_best[8];
    if (l == 0) s_best[w] = best;
    __syncthreads();
    if (threadIdx.x == 0) {
        unsigned long long b = s_best[0];
        #pragma unroll
        for (int i = 1; i < 8; i++) if (s_best[i] > b) b = s_best[i];
        if (b != 0ull) {
            g_keys[qorig] = b;
            unsigned bp = (unsigned)(~b);           // low 32 bits = ~best cand
            int bi = bp / HP, bj = bp % HP;
            g_delta[qorig] = (bi - qpi) * WW + (bj - qpj);
        }
    }
}

// ---------------- K4: output assembly (delta-based, 2-channel groups) --------
__global__ void __launch_bounds__(128) output_kernel(const float* __restrict__ low,
                                                     float* __restrict__ out) {
    if (blockIdx.x == 0 && blockIdx.y == 0 && threadIdx.x == 0) {
        g_qcount = 0;                     // consumed only by next replay's prep
        g_ccount = 0;
    }
    int pix = blockIdx.x * blockDim.x + threadIdx.x;
    if (pix >= HW) return;
    int y = pix / WW, x = pix % WW;
    int c0 = blockIdx.y * 2;

    int   offr[16];
    bool  ok[16];
    float cnt = 0.f;
    #pragma unroll
    for (int t = 0; t < 16; t++) {
        int di = t >> 2, dj = t & 3;
        int i = y - di, j = x - dj;
        bool o = (i >= 0) && (i < HP) && (j >= 0) && (j < HP);
        int p = o ? (i * HP + j) : 0;
        o = o && g_valid[p];
        ok[t] = o;
        offr[t] = o ? (pix + g_delta[p]) : 0;
        if (o) cnt += 1.f;
    }

    if (cnt == 0.f) {
        #pragma unroll
        for (int c = 0; c < 2; c++)
            out[(c0 + c) * HW + pix] = low[(c0 + c) * HW + pix];
        return;
    }
    float inv = 1.f / (cnt + EPSF);
    #pragma unroll
    for (int c = 0; c < 2; c++) {
        const float* lc = low + (c0 + c) * HW;
        float a = 0.f;
        #pragma unroll
        for (int t = 0; t < 16; t++)
            if (ok[t]) a += lc[offr[t]];
        out[(c0 + c) * HW + pix] = a * inv;
    }
}

// ---------------- launcher ---------------------------------------------------
extern "C" void kernel_launch(void* const* d_in, const int* in_sizes, int n_in,
                              void* d_out, int out_size) {
    const float* low  = (const float*)d_in[0];
    const float* high = (const float*)d_in[1];
    const int*   mask = (const int*)d_in[2];
    float*       out  = (float*)d_out;

    cudaFuncSetAttribute(gemm_h_kernel,
                         cudaFuncAttributeMaxDynamicSharedMemorySize, SMEM_TOTAL);

    prep_kernel<<<(NP * 32 + 255) / 256, 256>>>(low, high, mask);
    gemm_h_kernel<<<592, 128, SMEM_TOTAL>>>();
    rescore_kernel<<<NP, 256>>>(low, high);
    output_kernel<<<dim3((HW + 127) / 128, 16), 128>>>(low, out);
}